// round 16
// baseline (speedup 1.0000x reference)
#include <cuda_runtime.h>
#include <math.h>
#include <stdint.h>

// Problem constants
#define H_TOT 1024
#define NH    16
#define HD    64
#define B_SZ  8
#define SQ    1024
#define SKV   1024

// Arch gate: tcgen05 only exists in the arch-SPECIFIC (sm_103a) compilation
// pass. The generic compute_103 PTX pass gets SIMT fallback bodies.
#if defined(__CUDA_ARCH__) && \
    (defined(__CUDA_ARCH_FEAT_SM103_ALL) || defined(__CUDA_ARCH_FEAT_SM100_ALL) || \
     defined(__CUDA_ARCH_SPECIFIC__))
#define USE_TCGEN05 1
#else
#define USE_TCGEN05 0
#endif

// Scratch for Q/K/V projections: [B*S, H] row-major, head h at cols h*64..h*64+63
__device__ float g_Q[B_SZ * SQ * H_TOT];
__device__ float g_K[B_SZ * SKV * H_TOT];
__device__ float g_V[B_SZ * SKV * H_TOT];

// ===========================================================================
// Inline PTX helpers
// ===========================================================================
__device__ __forceinline__ uint32_t smem_u32(const void* p) {
    uint32_t a;
    asm("{ .reg .u64 t; cvta.to.shared.u64 t, %1; cvt.u32.u64 %0, t; }"
        : "=r"(a) : "l"(p));
    return a;
}
__device__ __forceinline__ uint32_t elect_one() {
    uint32_t p;
    asm volatile("{ .reg .pred p; elect.sync _|p, 0xFFFFFFFF; selp.b32 %0, 1, 0, p; }"
                 : "=r"(p));
    return p;
}
__device__ __forceinline__ uint32_t f2tf32(float f) {
    uint32_t r;
    asm("cvt.rn.tf32.f32 %0, %1;" : "=r"(r) : "f"(f));
    return r;
}
#if USE_TCGEN05
__device__ __forceinline__ void mma_tf32_ss(uint32_t d, uint64_t ad, uint64_t bd,
                                            uint32_t idesc, uint32_t en) {
    asm volatile(
        "{\n\t.reg .pred p;\n\tsetp.ne.u32 p, %4, 0;\n\t"
        "tcgen05.mma.cta_group::1.kind::tf32 [%0], %1, %2, %3, p;\n\t}"
        :: "r"(d), "l"(ad), "l"(bd), "r"(idesc), "r"(en) : "memory");
}
#endif

#define TCG_ALLOC(smem_addr, ncols) \
    asm volatile("tcgen05.alloc.cta_group::1.sync.aligned.shared::cta.b32 [%0], %1;" \
                 :: "r"(smem_addr), "r"((uint32_t)(ncols)) : "memory")
#define TCG_DEALLOC(tmem, ncols) \
    asm volatile("tcgen05.dealloc.cta_group::1.sync.aligned.b32 %0, %1;" \
                 :: "r"(tmem), "r"((uint32_t)(ncols)))
#define TCG_RELINQ() \
    asm volatile("tcgen05.relinquish_alloc_permit.cta_group::1.sync.aligned;")
#define TCG_COMMIT(mbar) \
    asm volatile("tcgen05.commit.cta_group::1.mbarrier::arrive::one.shared::cluster.b64 [%0];" \
                 :: "r"(mbar) : "memory")
#define TCG_FENCE_AFTER() \
    asm volatile("tcgen05.fence::after_thread_sync;" ::: "memory")
#define TCG_FENCE_BEFORE() \
    asm volatile("tcgen05.fence::before_thread_sync;" ::: "memory")
#define TCG_WAIT_LD() \
    asm volatile("tcgen05.wait::ld.sync.aligned;" ::: "memory")
#define FENCE_PROXY_ASYNC() \
    asm volatile("fence.proxy.async.shared::cta;" ::: "memory")
#define MBAR_INIT(mbar, cnt) \
    asm volatile("mbarrier.init.shared.b64 [%0], %1;" \
                 :: "r"(mbar), "r"((uint32_t)(cnt)) : "memory")
#define MBAR_WAIT(mbar, par) do {                                              \
    uint32_t _m = (mbar); uint32_t _p = (par); uint32_t _done;                 \
    asm volatile(                                                              \
        "{\n\t.reg .pred p;\n\t"                                               \
        "mbarrier.try_wait.parity.acquire.cta.shared::cta.b64 p, [%1], %2;\n\t"\
        "selp.b32 %0, 1, 0, p;\n\t}"                                           \
        : "=r"(_done) : "r"(_m), "r"(_p) : "memory");                          \
    if (!_done) {                                                              \
        asm volatile(                                                          \
            "{\n\t.reg .pred P1;\n\t"                                          \
            "WL_%=:\n\t"                                                       \
            "mbarrier.try_wait.parity.acquire.cta.shared::cta.b64 P1, [%0], %1, 0x989680;\n\t" \
            "@P1 bra.uni WD_%=;\n\t"                                           \
            "bra.uni WL_%=;\n\t"                                               \
            "WD_%=:\n\t}"                                                      \
            :: "r"(_m), "r"(_p) : "memory");                                   \
    }                                                                          \
} while (0)

#define TCG_LD_32X32B_X32(r, tmem_addr) \
    asm volatile( \
        "tcgen05.ld.sync.aligned.32x32b.x32.b32 " \
        "{%0, %1, %2, %3, %4, %5, %6, %7, " \
        " %8, %9, %10, %11, %12, %13, %14, %15, " \
        " %16, %17, %18, %19, %20, %21, %22, %23, " \
        " %24, %25, %26, %27, %28, %29, %30, %31}, [%32];" \
        : "=r"((r)[0]),  "=r"((r)[1]),  "=r"((r)[2]),  "=r"((r)[3]), \
          "=r"((r)[4]),  "=r"((r)[5]),  "=r"((r)[6]),  "=r"((r)[7]), \
          "=r"((r)[8]),  "=r"((r)[9]),  "=r"((r)[10]), "=r"((r)[11]), \
          "=r"((r)[12]), "=r"((r)[13]), "=r"((r)[14]), "=r"((r)[15]), \
          "=r"((r)[16]), "=r"((r)[17]), "=r"((r)[18]), "=r"((r)[19]), \
          "=r"((r)[20]), "=r"((r)[21]), "=r"((r)[22]), "=r"((r)[23]), \
          "=r"((r)[24]), "=r"((r)[25]), "=r"((r)[26]), "=r"((r)[27]), \
          "=r"((r)[28]), "=r"((r)[29]), "=r"((r)[30]), "=r"((r)[31]) \
        : "r"(tmem_addr))

// SW128 K-major smem descriptor: layout=2, version=1, SBO=64, LBO=1
__device__ __forceinline__ uint64_t smem_desc_sw128(uint32_t addr) {
    const uint64_t base =
        (uint64_t(2)  << 61) | (uint64_t(1) << 46) |
        (uint64_t(64) << 32) | (uint64_t(1) << 16);
    return base | ((uint64_t)(addr >> 4) & 0x3FFF);
}

// ===========================================================================
// GEMM: C[m,n] = sum_k A[m,k]*W[n,k] + bias[n]   (R14 version: WIN, ~189us)
// tcgen05 tf32 + register-prefetched feed.
// ===========================================================================
#define GK_CHUNK 32
#define GSM_TMEM 0
#define GSM_MBAR 8
#define GSM_A    1024
#define GSM_B    (1024 + 2 * 16384)
#define GSM_TOTAL (1024 + 4 * 16384)

// idesc: c=F32(1<<4), a=TF32(2<<7), b=TF32(2<<10), N=128 (16<<17), M=128 (8<<24)
#define GIDESC ((1u << 4) | (2u << 7) | (2u << 10) | (16u << 17) | (8u << 24))

__global__ __launch_bounds__(256, 2)
void gemm_tf32_kernel(const float* __restrict__ A,
                      const float* __restrict__ W,
                      const float* __restrict__ bias,
                      float* __restrict__ C)
{
#if USE_TCGEN05
    extern __shared__ char smem[];
    const uint32_t smem_base = smem_u32(smem);
    const int tid = threadIdx.x;
    const int wid = tid >> 5;
    const int lid = tid & 31;
    const int rowBase = blockIdx.y << 7;
    const int colBase = blockIdx.x << 7;

    if (wid == 0) {
        TCG_ALLOC(smem_base + GSM_TMEM, 128);
        TCG_RELINQ();
    }
    if (tid == 0) {
        MBAR_INIT(smem_base + GSM_MBAR, 1);
        MBAR_INIT(smem_base + GSM_MBAR + 8, 1);
    }
    __syncthreads();
    uint32_t tmem_base;
    asm volatile("ld.shared.b32 %0, [%1];"
                 : "=r"(tmem_base) : "r"(smem_base + GSM_TMEM));

    const float* Ag = A + (size_t)rowBase * H_TOT;
    const float* Wg = W + (size_t)colBase * H_TOT;

    const int pr = tid >> 3;          // 0..31 (base row)
    const int pc = (tid & 7) << 2;    // 0..28 (k offset within chunk)

    // prefetch chunk 0 into registers
    float4 pa[4], pw[4];
#pragma unroll
    for (int u = 0; u < 4; u++) {
        pa[u] = *(const float4*)(Ag + (size_t)(pr + u * 32) * H_TOT + pc);
        pw[u] = *(const float4*)(Wg + (size_t)(pr + u * 32) * H_TOT + pc);
    }

    int ph[2] = {0, 0};

    for (int t = 0; t < H_TOT / GK_CHUNK; t++) {
        const int buf = t & 1;
        const uint32_t mbar = smem_base + GSM_MBAR + buf * 8;
        if (t >= 2) {                 // MMA of chunk t-2 (same buffer) done?
            MBAR_WAIT(mbar, ph[buf]);
            ph[buf] ^= 1;
        }
        char* aBuf = smem + GSM_A + buf * 16384;
        char* bBuf = smem + GSM_B + buf * 16384;

        // store prefetched chunk t
#pragma unroll
        for (int u = 0; u < 4; u++) {
            int rr = pr + u * 32;
            uint32_t off = (rr << 7) + (pc << 2);
            uint32_t sw = off ^ ((off >> 3) & 0x70);
            uint4 at, wt;
            at.x = f2tf32(pa[u].x); at.y = f2tf32(pa[u].y);
            at.z = f2tf32(pa[u].z); at.w = f2tf32(pa[u].w);
            wt.x = f2tf32(pw[u].x); wt.y = f2tf32(pw[u].y);
            wt.z = f2tf32(pw[u].z); wt.w = f2tf32(pw[u].w);
            *(uint4*)(aBuf + sw) = at;
            *(uint4*)(bBuf + sw) = wt;
        }
        // prefetch chunk t+1 (latency hides behind sync + MMA + next wait)
        if (t + 1 < H_TOT / GK_CHUNK) {
            const int ktn = (t + 1) * GK_CHUNK;
#pragma unroll
            for (int u = 0; u < 4; u++) {
                pa[u] = *(const float4*)(Ag + (size_t)(pr + u * 32) * H_TOT + ktn + pc);
                pw[u] = *(const float4*)(Wg + (size_t)(pr + u * 32) * H_TOT + ktn + pc);
            }
        }
        FENCE_PROXY_ASYNC();
        __syncthreads();

        if (wid == 0 && elect_one()) {
            uint64_t ad = smem_desc_sw128(smem_base + GSM_A + buf * 16384);
            uint64_t bd = smem_desc_sw128(smem_base + GSM_B + buf * 16384);
#pragma unroll
            for (int s = 0; s < 4; s++) {
                mma_tf32_ss(tmem_base, ad + s * 2, bd + s * 2, GIDESC,
                            (t > 0) || (s > 0));
            }
            TCG_COMMIT(mbar);
        }
    }

    MBAR_WAIT(smem_base + GSM_MBAR + 8, ph[1]);
    __syncthreads();

    if (wid < 4) {
        TCG_FENCE_AFTER();
        const int row = rowBase + wid * 32 + lid;
        float* Crow = C + (size_t)row * H_TOT + colBase;
#pragma unroll
        for (int cb = 0; cb < 128; cb += 32) {
            uint32_t r[32];
            TCG_LD_32X32B_X32(r, tmem_base + cb);
            TCG_WAIT_LD();
#pragma unroll
            for (int i = 0; i < 8; i++) {
                float4 o;
                o.x = __uint_as_float(r[4 * i + 0]) + __ldg(bias + colBase + cb + 4 * i + 0);
                o.y = __uint_as_float(r[4 * i + 1]) + __ldg(bias + colBase + cb + 4 * i + 1);
                o.z = __uint_as_float(r[4 * i + 2]) + __ldg(bias + colBase + cb + 4 * i + 2);
                o.w = __uint_as_float(r[4 * i + 3]) + __ldg(bias + colBase + cb + 4 * i + 3);
                *(float4*)(Crow + cb + 4 * i) = o;
            }
        }
        TCG_FENCE_BEFORE();
    }
    __syncthreads();
    if (wid == 0) {
        TCG_DEALLOC(tmem_base, 128);
    }
#else
    // SIMT fp32 fallback (generic compute_103 PTX; never runs on GB300)
    extern __shared__ char smemraw[];
    float (*As)[128] = (float (*)[128])(smemraw);
    float (*Bs)[128] = (float (*)[128])(smemraw + 16 * 128 * sizeof(float));
    const int K = H_TOT;
    const int tid = threadIdx.x;
    const int ty = tid >> 4;
    const int tx = tid & 15;
    const int rowBase = blockIdx.y << 7;
    const int colBase = blockIdx.x << 7;
    const float* Ag = A + (size_t)rowBase * K;
    const float* Wg = W + (size_t)colBase * K;
    const int lr = tid >> 1;
    const int lc = (tid & 1) << 3;
    float acc[8][8];
#pragma unroll
    for (int i = 0; i < 8; i++)
#pragma unroll
        for (int j = 0; j < 8; j++) acc[i][j] = 0.f;
    for (int kt = 0; kt < K; kt += 16) {
        const float4 a0 = *(const float4*)(Ag + (size_t)lr * K + kt + lc);
        const float4 a1 = *(const float4*)(Ag + (size_t)lr * K + kt + lc + 4);
        const float4 b0 = *(const float4*)(Wg + (size_t)lr * K + kt + lc);
        const float4 b1 = *(const float4*)(Wg + (size_t)lr * K + kt + lc + 4);
        __syncthreads();
        As[lc + 0][lr] = a0.x; As[lc + 1][lr] = a0.y; As[lc + 2][lr] = a0.z; As[lc + 3][lr] = a0.w;
        As[lc + 4][lr] = a1.x; As[lc + 5][lr] = a1.y; As[lc + 6][lr] = a1.z; As[lc + 7][lr] = a1.w;
        Bs[lc + 0][lr] = b0.x; Bs[lc + 1][lr] = b0.y; Bs[lc + 2][lr] = b0.z; Bs[lc + 3][lr] = b0.w;
        Bs[lc + 4][lr] = b1.x; Bs[lc + 5][lr] = b1.y; Bs[lc + 6][lr] = b1.z; Bs[lc + 7][lr] = b1.w;
        __syncthreads();
#pragma unroll
        for (int k = 0; k < 16; k++) {
            float af[8], bf[8];
#pragma unroll
            for (int i = 0; i < 8; i++) af[i] = As[k][ty * 8 + i];
#pragma unroll
            for (int j = 0; j < 8; j++) bf[j] = Bs[k][j * 16 + tx];
#pragma unroll
            for (int i = 0; i < 8; i++)
#pragma unroll
                for (int j = 0; j < 8; j++)
                    acc[i][j] = fmaf(af[i], bf[j], acc[i][j]);
        }
    }
#pragma unroll
    for (int j = 0; j < 8; j++) {
        const int col = colBase + j * 16 + tx;
        const float bv = bias[col];
#pragma unroll
        for (int i = 0; i < 8; i++) {
            const int row = rowBase + ty * 8 + i;
            C[(size_t)row * H_TOT + col] = acc[i][j] + bv;
        }
    }
#endif
}

// ===========================================================================
// tcgen05 tf32 flash attention — EXACT R12 version (251us, regs 203): 256
// threads, split-column softmax, single-buffered, serial per-tile chain.
// (Pipelining retried twice, regressed twice — register-pressure bound.)
// ===========================================================================
#define ASM_TMEM  0
#define ASM_MBAR0 8
#define ASM_MBAR1 16
#define ASM_MASK  32                      // 128 floats
#define ASM_RED   1024                    // redM[256] + redS[256] floats
#define ASM_Q     4096                    // 2 k-blocks x 16KB = 32KB
#define ASM_K     (ASM_Q + 32768)
#define ASM_V     (ASM_K + 32768)         // 4 k-blocks x 8KB
#define ASM_P     (ASM_V + 32768)         // 4 k-blocks x 16KB = 64KB
#define ASM_TOTAL (ASM_P + 65536)         // 167936 B

// idesc: N=128 for S, N=64 for PV
#define AIDESC_S  ((1u << 4) | (2u << 7) | (2u << 10) | (16u << 17) | (8u << 24))
#define AIDESC_PV ((1u << 4) | (2u << 7) | (2u << 10) | ( 8u << 17) | (8u << 24))

__global__ __launch_bounds__(256, 1)
void attention_kernel(const float* __restrict__ mask, float* __restrict__ out)
{
#if USE_TCGEN05
    extern __shared__ char smem[];
    const uint32_t smem_base = smem_u32(smem);
    float* msk  = (float*)(smem + ASM_MASK);
    float* redM = (float*)(smem + ASM_RED);        // [2][128]
    float* redS = redM + 256;                      // [2][128]

    const int tid = threadIdx.x;
    const int wid = tid >> 5;
    const int wg  = tid >> 7;        // 0 or 1: column half
    const int wg_tid = tid & 127;    // row owned by this thread
    const int qTile = blockIdx.x;
    const int h = blockIdx.y;
    const int b = blockIdx.z;

    const size_t qOff   = ((size_t)(b * SQ) + qTile * 128) * H_TOT + h * HD;
    const size_t kvOff0 = (size_t)(b * SKV) * H_TOT + h * HD;

    if (wid == 0) {
        TCG_ALLOC(smem_base + ASM_TMEM, 256);
        TCG_RELINQ();
    }
    if (tid == 0) {
        MBAR_INIT(smem_base + ASM_MBAR0, 1);
        MBAR_INIT(smem_base + ASM_MBAR1, 1);
    }
    __syncthreads();
    uint32_t tmem_base;
    asm volatile("ld.shared.b32 %0, [%1];"
                 : "=r"(tmem_base) : "r"(smem_base + ASM_TMEM));
    const uint32_t tmem_S = tmem_base;        // cols 0..127
    const uint32_t tmem_D = tmem_base + 128;  // cols 128..191

    // ---- Q feed (once): rows=q, K-major, 2 k-blocks of 16KB ----
#pragma unroll
    for (int u = 0; u < 8; u++) {
        int lin = tid + u * 256;
        int r = lin >> 4;                   // 0..127
        int c4 = (lin & 15) << 2;           // 0..60
        float4 v = *(const float4*)(g_Q + qOff + (size_t)r * H_TOT + c4);
        int blk = c4 >> 5;
        int cc = c4 & 31;
        uint32_t off = (r << 7) + (cc << 2);
        uint32_t sw = off ^ ((off >> 3) & 0x70);
        uint4 qt;
        qt.x = f2tf32(v.x); qt.y = f2tf32(v.y);
        qt.z = f2tf32(v.z); qt.w = f2tf32(v.w);
        *(uint4*)(smem + ASM_Q + blk * 16384 + sw) = qt;
    }

    const int myRow = wg_tid;
    float m = -3.0e38f, l = 0.f;
    float O[32];
#pragma unroll
    for (int d = 0; d < 32; d++) O[d] = 0.f;

    int ph0 = 0, ph1 = 0;

    for (int kvt = 0; kvt < SKV / 128; kvt++) {
        const size_t kvOff = kvOff0 + (size_t)kvt * 128 * H_TOT;
        __syncthreads();   // prior tile's smem reads complete

        // ---- K feed: rows=kv, K-major over hd (2 blocks), 256 threads ----
#pragma unroll
        for (int u = 0; u < 8; u++) {
            int lin = tid + u * 256;
            int r = lin >> 4;
            int c4 = (lin & 15) << 2;
            float4 v = *(const float4*)(g_K + kvOff + (size_t)r * H_TOT + c4);
            int blk = c4 >> 5;
            int cc = c4 & 31;
            uint32_t off = (r << 7) + (cc << 2);
            uint32_t sw = off ^ ((off >> 3) & 0x70);
            uint4 kt;
            kt.x = f2tf32(v.x); kt.y = f2tf32(v.y);
            kt.z = f2tf32(v.z); kt.w = f2tf32(v.w);
            *(uint4*)(smem + ASM_K + blk * 16384 + sw) = kt;
        }
        // ---- V feed (transposed): kv = wg_tid, hd half per wg ----
#pragma unroll
        for (int u = 0; u < 8; u++) {
            int kv = wg_tid;
            int hd4 = wg * 32 + (u << 2);        // wg0: 0..28, wg1: 32..60
            float4 v = *(const float4*)(g_V + kvOff + (size_t)kv * H_TOT + hd4);
            int blk = kv >> 5;
            int c = kv & 31;
            uint32_t col = (uint32_t)(c << 2);
#pragma unroll
            for (int i = 0; i < 4; i++) {
                uint32_t off = ((uint32_t)(hd4 + i) << 7) + col;
                uint32_t sw = off ^ ((off >> 3) & 0x70);
                float fv = (i == 0) ? v.x : (i == 1) ? v.y : (i == 2) ? v.z : v.w;
                *(uint32_t*)(smem + ASM_V + blk * 8192 + sw) = f2tf32(fv);
            }
        }
        if (tid < 128)
            msk[tid] = __ldg(mask + b * SKV + kvt * 128 + tid);

        TCG_FENCE_BEFORE();
        FENCE_PROXY_ASYNC();
        __syncthreads();

        // ---- S-MMA: 2 k-blocks x 4 sub-K(=8) ----
        if (wid == 0 && elect_one()) {
            TCG_FENCE_AFTER();
#pragma unroll
            for (int kb = 0; kb < 2; kb++) {
                uint64_t ad = smem_desc_sw128(smem_base + ASM_Q + kb * 16384);
                uint64_t bd = smem_desc_sw128(smem_base + ASM_K + kb * 16384);
#pragma unroll
                for (int s = 0; s < 4; s++)
                    mma_tf32_ss(tmem_S, ad + s * 2, bd + s * 2, AIDESC_S,
                                (kb > 0) || (s > 0));
            }
            TCG_COMMIT(smem_base + ASM_MBAR0);
        }
        MBAR_WAIT(smem_base + ASM_MBAR0, ph0);
        ph0 ^= 1;
        TCG_FENCE_AFTER();

        // ---- LDTM S: this thread's half-row (64 cols at wg*64) ----
        float sv[64];
        {
            uint32_t tmp[32];
            TCG_LD_32X32B_X32(tmp, tmem_S + wg * 64);
#pragma unroll
            for (int i = 0; i < 32; i++) sv[i] = __uint_as_float(tmp[i]);
            TCG_LD_32X32B_X32(tmp, tmem_S + wg * 64 + 32);
#pragma unroll
            for (int i = 0; i < 32; i++) sv[32 + i] = __uint_as_float(tmp[i]);
            TCG_WAIT_LD();
        }

        // ---- online softmax (split across the two warpgroups) ----
        const float* mrow = msk + wg * 64;
        float rmax = -3.0e38f;
#pragma unroll
        for (int j = 0; j < 64; j++) {
            float s = fmaf(sv[j], 0.125f, mrow[j]);
            sv[j] = s;
            rmax = fmaxf(rmax, s);
        }
        redM[wg * 128 + myRow] = rmax;
        __syncthreads();
        const float full = fmaxf(redM[myRow], redM[128 + myRow]);
        const float mnew = fmaxf(m, full);
        const float alpha = __expf(m - mnew);
        float lsum = 0.f;
#pragma unroll
        for (int j = 0; j < 64; j++) {
            float p = __expf(sv[j] - mnew);
            sv[j] = p;
            lsum += p;
        }
        redS[wg * 128 + myRow] = lsum;
        __syncthreads();
        l = l * alpha + (redS[myRow] + redS[128 + myRow]);
        m = mnew;

        // ---- write P half-row to smem (A-operand layout) ----
#pragma unroll
        for (int jb = 0; jb < 16; jb++) {
            int j0 = jb << 2;
            int jg = wg * 64 + j0;                 // global S column
            int blk = jg >> 5;
            int c = jg & 31;
            uint32_t off = ((uint32_t)myRow << 7) + ((uint32_t)c << 2);
            uint32_t sw = off ^ ((off >> 3) & 0x70);
            uint4 pt;
            pt.x = f2tf32(sv[j0 + 0]); pt.y = f2tf32(sv[j0 + 1]);
            pt.z = f2tf32(sv[j0 + 2]); pt.w = f2tf32(sv[j0 + 3]);
            *(uint4*)(smem + ASM_P + blk * 16384 + sw) = pt;
        }
        TCG_FENCE_BEFORE();
        FENCE_PROXY_ASYNC();
        __syncthreads();

        // ---- PV-MMA: 4 k-blocks x 4 sub-K(=8), D overwritten ----
        if (wid == 0 && elect_one()) {
            TCG_FENCE_AFTER();
#pragma unroll
            for (int kb = 0; kb < 4; kb++) {
                uint64_t ad = smem_desc_sw128(smem_base + ASM_P + kb * 16384);
                uint64_t bd = smem_desc_sw128(smem_base + ASM_V + kb * 8192);
#pragma unroll
                for (int s = 0; s < 4; s++)
                    mma_tf32_ss(tmem_D, ad + s * 2, bd + s * 2, AIDESC_PV,
                                (kb > 0) || (s > 0));
            }
            TCG_COMMIT(smem_base + ASM_MBAR1);
        }
        MBAR_WAIT(smem_base + ASM_MBAR1, ph1);
        ph1 ^= 1;
        TCG_FENCE_AFTER();

        // ---- LDTM PV half-tile (32 cols at wg*32), accumulate O ----
        {
            uint32_t d0[32];
            TCG_LD_32X32B_X32(d0, tmem_D + wg * 32);
            TCG_WAIT_LD();
#pragma unroll
            for (int i = 0; i < 32; i++)
                O[i] = fmaf(O[i], alpha, __uint_as_float(d0[i]));
        }
        TCG_FENCE_BEFORE();
    }

    // ---- epilogue: stage O/l to smem, coalesced store ----
    __syncthreads();
    float* stage = (float*)(smem + ASM_P);   // P region dead now
    const float inv = 1.0f / l;
#pragma unroll
    for (int d = 0; d < 32; d++)
        stage[myRow * 68 + wg * 32 + d] = O[d] * inv;
    __syncthreads();

    const size_t row0 = (size_t)(b * SQ) + qTile * 128;
#pragma unroll
    for (int u = 0; u < 8; u++) {
        int lin = tid + u * 256;
        int r = lin >> 4;
        int c4 = (lin & 15) << 2;
        float4 o = *(const float4*)(stage + r * 68 + c4);
        *(float4*)(out + (row0 + r) * H_TOT + h * HD + c4) = o;
    }

    __syncthreads();
    if (wid == 0) {
        TCG_DEALLOC(tmem_base, 256);
    }
#else
    // Naive SIMT fallback (generic compute_103 PTX; never runs on GB300).
    const int tid = threadIdx.x;
    if (tid < 128) {
        const int qTile = blockIdx.x, h = blockIdx.y, b = blockIdx.z;
        const int qr = qTile * 128 + tid;
        const size_t qOff = ((size_t)(b * SQ) + qr) * H_TOT + h * HD;
        const size_t kvOff0 = (size_t)(b * SKV) * H_TOT + h * HD;
        float q[HD];
#pragma unroll
        for (int d = 0; d < HD; d++) q[d] = g_Q[qOff + d];
        float m = -3.0e38f, l = 0.f, O[HD];
#pragma unroll
        for (int d = 0; d < HD; d++) O[d] = 0.f;
        for (int kv = 0; kv < SKV; kv++) {
            const float* kp = g_K + kvOff0 + (size_t)kv * H_TOT;
            float s = 0.f;
#pragma unroll
            for (int d = 0; d < HD; d++) s = fmaf(q[d], kp[d], s);
            s = s * 0.125f + mask[b * SKV + kv];
            float mnew = fmaxf(m, s);
            float alpha = __expf(m - mnew);
            float p = __expf(s - mnew);
            l = l * alpha + p;
            const float* vp = g_V + kvOff0 + (size_t)kv * H_TOT;
#pragma unroll
            for (int d = 0; d < HD; d++) O[d] = O[d] * alpha + p * vp[d];
            m = mnew;
        }
        const float inv = 1.0f / l;
        float* op = out + ((size_t)(b * SQ) + qr) * H_TOT + h * HD;
#pragma unroll
        for (int d = 0; d < HD; d++) op[d] = O[d] * inv;
    }
#endif
}

// ---------------------------------------------------------------------------
extern "C" void kernel_launch(void* const* d_in, const int* in_sizes, int n_in,
                              void* d_out, int out_size)
{
    const float* hs   = (const float*)d_in[0];
    const float* kvs  = (const float*)d_in[1];
    const float* mask = (const float*)d_in[2];
    const float* Wq   = (const float*)d_in[3];
    const float* bq   = (const float*)d_in[4];
    const float* Wk   = (const float*)d_in[5];
    const float* bk   = (const float*)d_in[6];
    const float* Wv   = (const float*)d_in[7];
    const float* bv   = (const float*)d_in[8];
    float* out = (float*)d_out;
    (void)in_sizes; (void)n_in; (void)out_size;

    float *Qp = nullptr, *Kp = nullptr, *Vp = nullptr;
    cudaGetSymbolAddress((void**)&Qp, g_Q);
    cudaGetSymbolAddress((void**)&Kp, g_K);
    cudaGetSymbolAddress((void**)&Vp, g_V);

    cudaFuncSetAttribute(gemm_tf32_kernel,
                         cudaFuncAttributeMaxDynamicSharedMemorySize,
                         GSM_TOTAL);
    cudaFuncSetAttribute(attention_kernel,
                         cudaFuncAttributeMaxDynamicSharedMemorySize,
                         ASM_TOTAL);

    dim3 ggrid(H_TOT / 128, (B_SZ * SQ) / 128);   // (8, 64) = 512 CTAs
    gemm_tf32_kernel<<<ggrid, 256, GSM_TOTAL>>>(hs,  Wq, bq, Qp);
    gemm_tf32_kernel<<<ggrid, 256, GSM_TOTAL>>>(kvs, Wk, bk, Kp);
    gemm_tf32_kernel<<<ggrid, 256, GSM_TOTAL>>>(kvs, Wv, bv, Vp);

    dim3 agrid(SQ / 128, NH, B_SZ);               // 1024 blocks
    attention_kernel<<<agrid, 256, ASM_TOTAL>>>(mask, out);
}

// round 17
// speedup vs baseline: 1.5341x; 1.5341x over previous
#include <cuda_runtime.h>
#include <math.h>
#include <stdint.h>

// Problem constants
#define H_TOT 1024
#define NH    16
#define HD    64
#define B_SZ  8
#define SQ    1024
#define SKV   1024

// Arch gate: tcgen05 only exists in the arch-SPECIFIC (sm_103a) compilation
// pass. The generic compute_103 PTX pass gets SIMT fallback bodies.
#if defined(__CUDA_ARCH__) && \
    (defined(__CUDA_ARCH_FEAT_SM103_ALL) || defined(__CUDA_ARCH_FEAT_SM100_ALL) || \
     defined(__CUDA_ARCH_SPECIFIC__))
#define USE_TCGEN05 1
#else
#define USE_TCGEN05 0
#endif

// Scratch for Q/K/V projections: [B*S, H] row-major, head h at cols h*64..h*64+63
__device__ float g_Q[B_SZ * SQ * H_TOT];
__device__ float g_K[B_SZ * SKV * H_TOT];
__device__ float g_V[B_SZ * SKV * H_TOT];

// ===========================================================================
// Inline PTX helpers
// ===========================================================================
__device__ __forceinline__ uint32_t smem_u32(const void* p) {
    uint32_t a;
    asm("{ .reg .u64 t; cvta.to.shared.u64 t, %1; cvt.u32.u64 %0, t; }"
        : "=r"(a) : "l"(p));
    return a;
}
__device__ __forceinline__ uint32_t elect_one() {
    uint32_t p;
    asm volatile("{ .reg .pred p; elect.sync _|p, 0xFFFFFFFF; selp.b32 %0, 1, 0, p; }"
                 : "=r"(p));
    return p;
}
__device__ __forceinline__ uint32_t f2tf32(float f) {
    uint32_t r;
    asm("cvt.rn.tf32.f32 %0, %1;" : "=r"(r) : "f"(f));
    return r;
}
#if USE_TCGEN05
__device__ __forceinline__ void mma_tf32_ss(uint32_t d, uint64_t ad, uint64_t bd,
                                            uint32_t idesc, uint32_t en) {
    asm volatile(
        "{\n\t.reg .pred p;\n\tsetp.ne.u32 p, %4, 0;\n\t"
        "tcgen05.mma.cta_group::1.kind::tf32 [%0], %1, %2, %3, p;\n\t}"
        :: "r"(d), "l"(ad), "l"(bd), "r"(idesc), "r"(en) : "memory");
}
#endif

#define TCG_ALLOC(smem_addr, ncols) \
    asm volatile("tcgen05.alloc.cta_group::1.sync.aligned.shared::cta.b32 [%0], %1;" \
                 :: "r"(smem_addr), "r"((uint32_t)(ncols)) : "memory")
#define TCG_DEALLOC(tmem, ncols) \
    asm volatile("tcgen05.dealloc.cta_group::1.sync.aligned.b32 %0, %1;" \
                 :: "r"(tmem), "r"((uint32_t)(ncols)))
#define TCG_RELINQ() \
    asm volatile("tcgen05.relinquish_alloc_permit.cta_group::1.sync.aligned;")
#define TCG_COMMIT(mbar) \
    asm volatile("tcgen05.commit.cta_group::1.mbarrier::arrive::one.shared::cluster.b64 [%0];" \
                 :: "r"(mbar) : "memory")
#define TCG_FENCE_AFTER() \
    asm volatile("tcgen05.fence::after_thread_sync;" ::: "memory")
#define TCG_FENCE_BEFORE() \
    asm volatile("tcgen05.fence::before_thread_sync;" ::: "memory")
#define TCG_WAIT_LD() \
    asm volatile("tcgen05.wait::ld.sync.aligned;" ::: "memory")
#define FENCE_PROXY_ASYNC() \
    asm volatile("fence.proxy.async.shared::cta;" ::: "memory")
#define MBAR_INIT(mbar, cnt) \
    asm volatile("mbarrier.init.shared.b64 [%0], %1;" \
                 :: "r"(mbar), "r"((uint32_t)(cnt)) : "memory")
#define MBAR_WAIT(mbar, par) do {                                              \
    uint32_t _m = (mbar); uint32_t _p = (par); uint32_t _done;                 \
    asm volatile(                                                              \
        "{\n\t.reg .pred p;\n\t"                                               \
        "mbarrier.try_wait.parity.acquire.cta.shared::cta.b64 p, [%1], %2;\n\t"\
        "selp.b32 %0, 1, 0, p;\n\t}"                                           \
        : "=r"(_done) : "r"(_m), "r"(_p) : "memory");                          \
    if (!_done) {                                                              \
        asm volatile(                                                          \
            "{\n\t.reg .pred P1;\n\t"                                          \
            "WL_%=:\n\t"                                                       \
            "mbarrier.try_wait.parity.acquire.cta.shared::cta.b64 P1, [%0], %1, 0x989680;\n\t" \
            "@P1 bra.uni WD_%=;\n\t"                                           \
            "bra.uni WL_%=;\n\t"                                               \
            "WD_%=:\n\t}"                                                      \
            :: "r"(_m), "r"(_p) : "memory");                                   \
    }                                                                          \
} while (0)

#define TCG_LD_32X32B_X32(r, tmem_addr) \
    asm volatile( \
        "tcgen05.ld.sync.aligned.32x32b.x32.b32 " \
        "{%0, %1, %2, %3, %4, %5, %6, %7, " \
        " %8, %9, %10, %11, %12, %13, %14, %15, " \
        " %16, %17, %18, %19, %20, %21, %22, %23, " \
        " %24, %25, %26, %27, %28, %29, %30, %31}, [%32];" \
        : "=r"((r)[0]),  "=r"((r)[1]),  "=r"((r)[2]),  "=r"((r)[3]), \
          "=r"((r)[4]),  "=r"((r)[5]),  "=r"((r)[6]),  "=r"((r)[7]), \
          "=r"((r)[8]),  "=r"((r)[9]),  "=r"((r)[10]), "=r"((r)[11]), \
          "=r"((r)[12]), "=r"((r)[13]), "=r"((r)[14]), "=r"((r)[15]), \
          "=r"((r)[16]), "=r"((r)[17]), "=r"((r)[18]), "=r"((r)[19]), \
          "=r"((r)[20]), "=r"((r)[21]), "=r"((r)[22]), "=r"((r)[23]), \
          "=r"((r)[24]), "=r"((r)[25]), "=r"((r)[26]), "=r"((r)[27]), \
          "=r"((r)[28]), "=r"((r)[29]), "=r"((r)[30]), "=r"((r)[31]) \
        : "r"(tmem_addr))

// SW128 K-major smem descriptor: layout=2, version=1, SBO=64, LBO=1
__device__ __forceinline__ uint64_t smem_desc_sw128(uint32_t addr) {
    const uint64_t base =
        (uint64_t(2)  << 61) | (uint64_t(1) << 46) |
        (uint64_t(64) << 32) | (uint64_t(1) << 16);
    return base | ((uint64_t)(addr >> 4) & 0x3FFF);
}

// ===========================================================================
// GEMM: C[m,n] = sum_k A[m,k]*W[n,k] + bias[n]   (R14 body: measured 63us/ea)
// blockIdx.z selects (W,bias,C) so K and V projections share one launch and
// their A-tile (kvs) L2 footprint.
// ===========================================================================
#define GK_CHUNK 32
#define GSM_TMEM 0
#define GSM_MBAR 8
#define GSM_A    1024
#define GSM_B    (1024 + 2 * 16384)
#define GSM_TOTAL (1024 + 4 * 16384)

// idesc: c=F32(1<<4), a=TF32(2<<7), b=TF32(2<<10), N=128 (16<<17), M=128 (8<<24)
#define GIDESC ((1u << 4) | (2u << 7) | (2u << 10) | (16u << 17) | (8u << 24))

__global__ __launch_bounds__(256, 2)
void gemm_tf32_kernel(const float* __restrict__ A,
                      const float* __restrict__ W0,
                      const float* __restrict__ b0,
                      float* __restrict__ C0,
                      const float* __restrict__ W1,
                      const float* __restrict__ b1,
                      float* __restrict__ C1)
{
    const float* W    = (blockIdx.z == 0) ? W0 : W1;
    const float* bias = (blockIdx.z == 0) ? b0 : b1;
    float*       C    = (blockIdx.z == 0) ? C0 : C1;
#if USE_TCGEN05
    extern __shared__ char smem[];
    const uint32_t smem_base = smem_u32(smem);
    const int tid = threadIdx.x;
    const int wid = tid >> 5;
    const int lid = tid & 31;
    const int rowBase = blockIdx.y << 7;
    const int colBase = blockIdx.x << 7;

    if (wid == 0) {
        TCG_ALLOC(smem_base + GSM_TMEM, 128);
        TCG_RELINQ();
    }
    if (tid == 0) {
        MBAR_INIT(smem_base + GSM_MBAR, 1);
        MBAR_INIT(smem_base + GSM_MBAR + 8, 1);
    }
    __syncthreads();
    uint32_t tmem_base;
    asm volatile("ld.shared.b32 %0, [%1];"
                 : "=r"(tmem_base) : "r"(smem_base + GSM_TMEM));

    const float* Ag = A + (size_t)rowBase * H_TOT;
    const float* Wg = W + (size_t)colBase * H_TOT;

    const int pr = tid >> 3;          // 0..31 (base row)
    const int pc = (tid & 7) << 2;    // 0..28 (k offset within chunk)

    // prefetch chunk 0 into registers
    float4 pa[4], pw[4];
#pragma unroll
    for (int u = 0; u < 4; u++) {
        pa[u] = *(const float4*)(Ag + (size_t)(pr + u * 32) * H_TOT + pc);
        pw[u] = *(const float4*)(Wg + (size_t)(pr + u * 32) * H_TOT + pc);
    }

    int ph[2] = {0, 0};

    for (int t = 0; t < H_TOT / GK_CHUNK; t++) {
        const int buf = t & 1;
        const uint32_t mbar = smem_base + GSM_MBAR + buf * 8;
        if (t >= 2) {                 // MMA of chunk t-2 (same buffer) done?
            MBAR_WAIT(mbar, ph[buf]);
            ph[buf] ^= 1;
        }
        char* aBuf = smem + GSM_A + buf * 16384;
        char* bBuf = smem + GSM_B + buf * 16384;

        // store prefetched chunk t
#pragma unroll
        for (int u = 0; u < 4; u++) {
            int rr = pr + u * 32;
            uint32_t off = (rr << 7) + (pc << 2);
            uint32_t sw = off ^ ((off >> 3) & 0x70);
            uint4 at, wt;
            at.x = f2tf32(pa[u].x); at.y = f2tf32(pa[u].y);
            at.z = f2tf32(pa[u].z); at.w = f2tf32(pa[u].w);
            wt.x = f2tf32(pw[u].x); wt.y = f2tf32(pw[u].y);
            wt.z = f2tf32(pw[u].z); wt.w = f2tf32(pw[u].w);
            *(uint4*)(aBuf + sw) = at;
            *(uint4*)(bBuf + sw) = wt;
        }
        // prefetch chunk t+1 (latency hides behind sync + MMA + next wait)
        if (t + 1 < H_TOT / GK_CHUNK) {
            const int ktn = (t + 1) * GK_CHUNK;
#pragma unroll
            for (int u = 0; u < 4; u++) {
                pa[u] = *(const float4*)(Ag + (size_t)(pr + u * 32) * H_TOT + ktn + pc);
                pw[u] = *(const float4*)(Wg + (size_t)(pr + u * 32) * H_TOT + ktn + pc);
            }
        }
        FENCE_PROXY_ASYNC();
        __syncthreads();

        if (wid == 0 && elect_one()) {
            uint64_t ad = smem_desc_sw128(smem_base + GSM_A + buf * 16384);
            uint64_t bd = smem_desc_sw128(smem_base + GSM_B + buf * 16384);
#pragma unroll
            for (int s = 0; s < 4; s++) {
                mma_tf32_ss(tmem_base, ad + s * 2, bd + s * 2, GIDESC,
                            (t > 0) || (s > 0));
            }
            TCG_COMMIT(mbar);
        }
    }

    MBAR_WAIT(smem_base + GSM_MBAR + 8, ph[1]);
    __syncthreads();

    if (wid < 4) {
        TCG_FENCE_AFTER();
        const int row = rowBase + wid * 32 + lid;
        float* Crow = C + (size_t)row * H_TOT + colBase;
#pragma unroll
        for (int cb = 0; cb < 128; cb += 32) {
            uint32_t r[32];
            TCG_LD_32X32B_X32(r, tmem_base + cb);
            TCG_WAIT_LD();
#pragma unroll
            for (int i = 0; i < 8; i++) {
                float4 o;
                o.x = __uint_as_float(r[4 * i + 0]) + __ldg(bias + colBase + cb + 4 * i + 0);
                o.y = __uint_as_float(r[4 * i + 1]) + __ldg(bias + colBase + cb + 4 * i + 1);
                o.z = __uint_as_float(r[4 * i + 2]) + __ldg(bias + colBase + cb + 4 * i + 2);
                o.w = __uint_as_float(r[4 * i + 3]) + __ldg(bias + colBase + cb + 4 * i + 3);
                *(float4*)(Crow + cb + 4 * i) = o;
            }
        }
        TCG_FENCE_BEFORE();
    }
    __syncthreads();
    if (wid == 0) {
        TCG_DEALLOC(tmem_base, 128);
    }
#else
    // SIMT fp32 fallback (generic compute_103 PTX; never runs on GB300)
    extern __shared__ char smemraw[];
    float (*As)[128] = (float (*)[128])(smemraw);
    float (*Bs)[128] = (float (*)[128])(smemraw + 16 * 128 * sizeof(float));
    const int K = H_TOT;
    const int tid = threadIdx.x;
    const int ty = tid >> 4;
    const int tx = tid & 15;
    const int rowBase = blockIdx.y << 7;
    const int colBase = blockIdx.x << 7;
    const float* Ag = A + (size_t)rowBase * K;
    const float* Wg = W + (size_t)colBase * K;
    const int lr = tid >> 1;
    const int lc = (tid & 1) << 3;
    float acc[8][8];
#pragma unroll
    for (int i = 0; i < 8; i++)
#pragma unroll
        for (int j = 0; j < 8; j++) acc[i][j] = 0.f;
    for (int kt = 0; kt < K; kt += 16) {
        const float4 a0 = *(const float4*)(Ag + (size_t)lr * K + kt + lc);
        const float4 a1 = *(const float4*)(Ag + (size_t)lr * K + kt + lc + 4);
        const float4 b0v = *(const float4*)(Wg + (size_t)lr * K + kt + lc);
        const float4 b1v = *(const float4*)(Wg + (size_t)lr * K + kt + lc + 4);
        __syncthreads();
        As[lc + 0][lr] = a0.x; As[lc + 1][lr] = a0.y; As[lc + 2][lr] = a0.z; As[lc + 3][lr] = a0.w;
        As[lc + 4][lr] = a1.x; As[lc + 5][lr] = a1.y; As[lc + 6][lr] = a1.z; As[lc + 7][lr] = a1.w;
        Bs[lc + 0][lr] = b0v.x; Bs[lc + 1][lr] = b0v.y; Bs[lc + 2][lr] = b0v.z; Bs[lc + 3][lr] = b0v.w;
        Bs[lc + 4][lr] = b1v.x; Bs[lc + 5][lr] = b1v.y; Bs[lc + 6][lr] = b1v.z; Bs[lc + 7][lr] = b1v.w;
        __syncthreads();
#pragma unroll
        for (int k = 0; k < 16; k++) {
            float af[8], bf[8];
#pragma unroll
            for (int i = 0; i < 8; i++) af[i] = As[k][ty * 8 + i];
#pragma unroll
            for (int j = 0; j < 8; j++) bf[j] = Bs[k][j * 16 + tx];
#pragma unroll
            for (int i = 0; i < 8; i++)
#pragma unroll
                for (int j = 0; j < 8; j++)
                    acc[i][j] = fmaf(af[i], bf[j], acc[i][j]);
        }
    }
#pragma unroll
    for (int j = 0; j < 8; j++) {
        const int col = colBase + j * 16 + tx;
        const float bv = bias[col];
#pragma unroll
        for (int i = 0; i < 8; i++) {
            const int row = rowBase + ty * 8 + i;
            C[(size_t)row * H_TOT + col] = acc[i][j] + bv;
        }
    }
#endif
}

// ===========================================================================
// tcgen05 tf32 flash attention — EXACT R12 body (best measured: 251us,
// regs 203): 256 threads, split-column softmax, single-buffered serial chain.
// (In-CTA pipelining retried twice, regressed twice — do not retry.)
// ===========================================================================
#define ASM_TMEM  0
#define ASM_MBAR0 8
#define ASM_MBAR1 16
#define ASM_MASK  32                      // 128 floats
#define ASM_RED   1024                    // redM[256] + redS[256] floats
#define ASM_Q     4096                    // 2 k-blocks x 16KB = 32KB
#define ASM_K     (ASM_Q + 32768)
#define ASM_V     (ASM_K + 32768)         // 4 k-blocks x 8KB
#define ASM_P     (ASM_V + 32768)         // 4 k-blocks x 16KB = 64KB
#define ASM_TOTAL (ASM_P + 65536)         // 167936 B

// idesc: N=128 for S, N=64 for PV
#define AIDESC_S  ((1u << 4) | (2u << 7) | (2u << 10) | (16u << 17) | (8u << 24))
#define AIDESC_PV ((1u << 4) | (2u << 7) | (2u << 10) | ( 8u << 17) | (8u << 24))

__global__ __launch_bounds__(256, 1)
void attention_kernel(const float* __restrict__ mask, float* __restrict__ out)
{
#if USE_TCGEN05
    extern __shared__ char smem[];
    const uint32_t smem_base = smem_u32(smem);
    float* msk  = (float*)(smem + ASM_MASK);
    float* redM = (float*)(smem + ASM_RED);        // [2][128]
    float* redS = redM + 256;                      // [2][128]

    const int tid = threadIdx.x;
    const int wid = tid >> 5;
    const int wg  = tid >> 7;        // 0 or 1: column half
    const int wg_tid = tid & 127;    // row owned by this thread
    const int qTile = blockIdx.x;
    const int h = blockIdx.y;
    const int b = blockIdx.z;

    const size_t qOff   = ((size_t)(b * SQ) + qTile * 128) * H_TOT + h * HD;
    const size_t kvOff0 = (size_t)(b * SKV) * H_TOT + h * HD;

    if (wid == 0) {
        TCG_ALLOC(smem_base + ASM_TMEM, 256);
        TCG_RELINQ();
    }
    if (tid == 0) {
        MBAR_INIT(smem_base + ASM_MBAR0, 1);
        MBAR_INIT(smem_base + ASM_MBAR1, 1);
    }
    __syncthreads();
    uint32_t tmem_base;
    asm volatile("ld.shared.b32 %0, [%1];"
                 : "=r"(tmem_base) : "r"(smem_base + ASM_TMEM));
    const uint32_t tmem_S = tmem_base;        // cols 0..127
    const uint32_t tmem_D = tmem_base + 128;  // cols 128..191

    // ---- Q feed (once): rows=q, K-major, 2 k-blocks of 16KB ----
#pragma unroll
    for (int u = 0; u < 8; u++) {
        int lin = tid + u * 256;
        int r = lin >> 4;                   // 0..127
        int c4 = (lin & 15) << 2;           // 0..60
        float4 v = *(const float4*)(g_Q + qOff + (size_t)r * H_TOT + c4);
        int blk = c4 >> 5;
        int cc = c4 & 31;
        uint32_t off = (r << 7) + (cc << 2);
        uint32_t sw = off ^ ((off >> 3) & 0x70);
        uint4 qt;
        qt.x = f2tf32(v.x); qt.y = f2tf32(v.y);
        qt.z = f2tf32(v.z); qt.w = f2tf32(v.w);
        *(uint4*)(smem + ASM_Q + blk * 16384 + sw) = qt;
    }

    const int myRow = wg_tid;
    float m = -3.0e38f, l = 0.f;
    float O[32];
#pragma unroll
    for (int d = 0; d < 32; d++) O[d] = 0.f;

    int ph0 = 0, ph1 = 0;

    for (int kvt = 0; kvt < SKV / 128; kvt++) {
        const size_t kvOff = kvOff0 + (size_t)kvt * 128 * H_TOT;
        __syncthreads();   // prior tile's smem reads complete

        // ---- K feed: rows=kv, K-major over hd (2 blocks), 256 threads ----
#pragma unroll
        for (int u = 0; u < 8; u++) {
            int lin = tid + u * 256;
            int r = lin >> 4;
            int c4 = (lin & 15) << 2;
            float4 v = *(const float4*)(g_K + kvOff + (size_t)r * H_TOT + c4);
            int blk = c4 >> 5;
            int cc = c4 & 31;
            uint32_t off = (r << 7) + (cc << 2);
            uint32_t sw = off ^ ((off >> 3) & 0x70);
            uint4 kt;
            kt.x = f2tf32(v.x); kt.y = f2tf32(v.y);
            kt.z = f2tf32(v.z); kt.w = f2tf32(v.w);
            *(uint4*)(smem + ASM_K + blk * 16384 + sw) = kt;
        }
        // ---- V feed (transposed): kv = wg_tid, hd half per wg ----
#pragma unroll
        for (int u = 0; u < 8; u++) {
            int kv = wg_tid;
            int hd4 = wg * 32 + (u << 2);        // wg0: 0..28, wg1: 32..60
            float4 v = *(const float4*)(g_V + kvOff + (size_t)kv * H_TOT + hd4);
            int blk = kv >> 5;
            int c = kv & 31;
            uint32_t col = (uint32_t)(c << 2);
#pragma unroll
            for (int i = 0; i < 4; i++) {
                uint32_t off = ((uint32_t)(hd4 + i) << 7) + col;
                uint32_t sw = off ^ ((off >> 3) & 0x70);
                float fv = (i == 0) ? v.x : (i == 1) ? v.y : (i == 2) ? v.z : v.w;
                *(uint32_t*)(smem + ASM_V + blk * 8192 + sw) = f2tf32(fv);
            }
        }
        if (tid < 128)
            msk[tid] = __ldg(mask + b * SKV + kvt * 128 + tid);

        TCG_FENCE_BEFORE();
        FENCE_PROXY_ASYNC();
        __syncthreads();

        // ---- S-MMA: 2 k-blocks x 4 sub-K(=8) ----
        if (wid == 0 && elect_one()) {
            TCG_FENCE_AFTER();
#pragma unroll
            for (int kb = 0; kb < 2; kb++) {
                uint64_t ad = smem_desc_sw128(smem_base + ASM_Q + kb * 16384);
                uint64_t bd = smem_desc_sw128(smem_base + ASM_K + kb * 16384);
#pragma unroll
                for (int s = 0; s < 4; s++)
                    mma_tf32_ss(tmem_S, ad + s * 2, bd + s * 2, AIDESC_S,
                                (kb > 0) || (s > 0));
            }
            TCG_COMMIT(smem_base + ASM_MBAR0);
        }
        MBAR_WAIT(smem_base + ASM_MBAR0, ph0);
        ph0 ^= 1;
        TCG_FENCE_AFTER();

        // ---- LDTM S: this thread's half-row (64 cols at wg*64) ----
        float sv[64];
        {
            uint32_t tmp[32];
            TCG_LD_32X32B_X32(tmp, tmem_S + wg * 64);
#pragma unroll
            for (int i = 0; i < 32; i++) sv[i] = __uint_as_float(tmp[i]);
            TCG_LD_32X32B_X32(tmp, tmem_S + wg * 64 + 32);
#pragma unroll
            for (int i = 0; i < 32; i++) sv[32 + i] = __uint_as_float(tmp[i]);
            TCG_WAIT_LD();
        }

        // ---- online softmax (split across the two warpgroups) ----
        const float* mrow = msk + wg * 64;
        float rmax = -3.0e38f;
#pragma unroll
        for (int j = 0; j < 64; j++) {
            float s = fmaf(sv[j], 0.125f, mrow[j]);
            sv[j] = s;
            rmax = fmaxf(rmax, s);
        }
        redM[wg * 128 + myRow] = rmax;
        __syncthreads();
        const float full = fmaxf(redM[myRow], redM[128 + myRow]);
        const float mnew = fmaxf(m, full);
        const float alpha = __expf(m - mnew);
        float lsum = 0.f;
#pragma unroll
        for (int j = 0; j < 64; j++) {
            float p = __expf(sv[j] - mnew);
            sv[j] = p;
            lsum += p;
        }
        redS[wg * 128 + myRow] = lsum;
        __syncthreads();
        l = l * alpha + (redS[myRow] + redS[128 + myRow]);
        m = mnew;

        // ---- write P half-row to smem (A-operand layout) ----
#pragma unroll
        for (int jb = 0; jb < 16; jb++) {
            int j0 = jb << 2;
            int jg = wg * 64 + j0;                 // global S column
            int blk = jg >> 5;
            int c = jg & 31;
            uint32_t off = ((uint32_t)myRow << 7) + ((uint32_t)c << 2);
            uint32_t sw = off ^ ((off >> 3) & 0x70);
            uint4 pt;
            pt.x = f2tf32(sv[j0 + 0]); pt.y = f2tf32(sv[j0 + 1]);
            pt.z = f2tf32(sv[j0 + 2]); pt.w = f2tf32(sv[j0 + 3]);
            *(uint4*)(smem + ASM_P + blk * 16384 + sw) = pt;
        }
        TCG_FENCE_BEFORE();
        FENCE_PROXY_ASYNC();
        __syncthreads();

        // ---- PV-MMA: 4 k-blocks x 4 sub-K(=8), D overwritten ----
        if (wid == 0 && elect_one()) {
            TCG_FENCE_AFTER();
#pragma unroll
            for (int kb = 0; kb < 4; kb++) {
                uint64_t ad = smem_desc_sw128(smem_base + ASM_P + kb * 16384);
                uint64_t bd = smem_desc_sw128(smem_base + ASM_V + kb * 8192);
#pragma unroll
                for (int s = 0; s < 4; s++)
                    mma_tf32_ss(tmem_D, ad + s * 2, bd + s * 2, AIDESC_PV,
                                (kb > 0) || (s > 0));
            }
            TCG_COMMIT(smem_base + ASM_MBAR1);
        }
        MBAR_WAIT(smem_base + ASM_MBAR1, ph1);
        ph1 ^= 1;
        TCG_FENCE_AFTER();

        // ---- LDTM PV half-tile (32 cols at wg*32), accumulate O ----
        {
            uint32_t d0[32];
            TCG_LD_32X32B_X32(d0, tmem_D + wg * 32);
            TCG_WAIT_LD();
#pragma unroll
            for (int i = 0; i < 32; i++)
                O[i] = fmaf(O[i], alpha, __uint_as_float(d0[i]));
        }
        TCG_FENCE_BEFORE();
    }

    // ---- epilogue: stage O/l to smem, coalesced store ----
    __syncthreads();
    float* stage = (float*)(smem + ASM_P);   // P region dead now
    const float inv = 1.0f / l;
#pragma unroll
    for (int d = 0; d < 32; d++)
        stage[myRow * 68 + wg * 32 + d] = O[d] * inv;
    __syncthreads();

    const size_t row0 = (size_t)(b * SQ) + qTile * 128;
#pragma unroll
    for (int u = 0; u < 8; u++) {
        int lin = tid + u * 256;
        int r = lin >> 4;
        int c4 = (lin & 15) << 2;
        float4 o = *(const float4*)(stage + r * 68 + c4);
        *(float4*)(out + (row0 + r) * H_TOT + h * HD + c4) = o;
    }

    __syncthreads();
    if (wid == 0) {
        TCG_DEALLOC(tmem_base, 256);
    }
#else
    // Naive SIMT fallback (generic compute_103 PTX; never runs on GB300).
    const int tid = threadIdx.x;
    if (tid < 128) {
        const int qTile = blockIdx.x, h = blockIdx.y, b = blockIdx.z;
        const int qr = qTile * 128 + tid;
        const size_t qOff = ((size_t)(b * SQ) + qr) * H_TOT + h * HD;
        const size_t kvOff0 = (size_t)(b * SKV) * H_TOT + h * HD;
        float q[HD];
#pragma unroll
        for (int d = 0; d < HD; d++) q[d] = g_Q[qOff + d];
        float m = -3.0e38f, l = 0.f, O[HD];
#pragma unroll
        for (int d = 0; d < HD; d++) O[d] = 0.f;
        for (int kv = 0; kv < SKV; kv++) {
            const float* kp = g_K + kvOff0 + (size_t)kv * H_TOT;
            float s = 0.f;
#pragma unroll
            for (int d = 0; d < HD; d++) s = fmaf(q[d], kp[d], s);
            s = s * 0.125f + mask[b * SKV + kv];
            float mnew = fmaxf(m, s);
            float alpha = __expf(m - mnew);
            float p = __expf(s - mnew);
            l = l * alpha + p;
            const float* vp = g_V + kvOff0 + (size_t)kv * H_TOT;
#pragma unroll
            for (int d = 0; d < HD; d++) O[d] = O[d] * alpha + p * vp[d];
            m = mnew;
        }
        const float inv = 1.0f / l;
        float* op = out + ((size_t)(b * SQ) + qr) * H_TOT + h * HD;
#pragma unroll
        for (int d = 0; d < HD; d++) op[d] = O[d] * inv;
    }
#endif
}

// ---------------------------------------------------------------------------
extern "C" void kernel_launch(void* const* d_in, const int* in_sizes, int n_in,
                              void* d_out, int out_size)
{
    const float* hs   = (const float*)d_in[0];
    const float* kvs  = (const float*)d_in[1];
    const float* mask = (const float*)d_in[2];
    const float* Wq   = (const float*)d_in[3];
    const float* bq   = (const float*)d_in[4];
    const float* Wk   = (const float*)d_in[5];
    const float* bk   = (const float*)d_in[6];
    const float* Wv   = (const float*)d_in[7];
    const float* bv   = (const float*)d_in[8];
    float* out = (float*)d_out;
    (void)in_sizes; (void)n_in; (void)out_size;

    float *Qp = nullptr, *Kp = nullptr, *Vp = nullptr;
    cudaGetSymbolAddress((void**)&Qp, g_Q);
    cudaGetSymbolAddress((void**)&Kp, g_K);
    cudaGetSymbolAddress((void**)&Vp, g_V);

    cudaFuncSetAttribute(gemm_tf32_kernel,
                         cudaFuncAttributeMaxDynamicSharedMemorySize,
                         GSM_TOTAL);
    cudaFuncSetAttribute(attention_kernel,
                         cudaFuncAttributeMaxDynamicSharedMemorySize,
                         ASM_TOTAL);

    // Q projection: grid (8, 64, 1)
    dim3 qgrid(H_TOT / 128, (B_SZ * SQ) / 128, 1);
    gemm_tf32_kernel<<<qgrid, 256, GSM_TOTAL>>>(hs, Wq, bq, Qp, Wq, bq, Qp);
    // K + V projections fused: grid (8, 64, 2) — z selects K vs V; both
    // z-slices read the same kvs A-tiles -> L2 reuse.
    dim3 kvgrid(H_TOT / 128, (B_SZ * SQ) / 128, 2);
    gemm_tf32_kernel<<<kvgrid, 256, GSM_TOTAL>>>(kvs, Wk, bk, Kp, Wv, bv, Vp);

    dim3 agrid(SQ / 128, NH, B_SZ);               // 1024 blocks
    attention_kernel<<<agrid, 256, ASM_TOTAL>>>(mask, out);
}